// round 10
// baseline (speedup 1.0000x reference)
#include <cuda_runtime.h>
#include <cuda_fp16.h>
#include <cstdint>

#define H    448
#define HH   (448*448)
#define CIN  64
#define COUT 64
#define NB   32
#define BS   14
#define HAL  18
#define NTHR 256

// ---- dynamic smem layout (bytes) ----
#define OFF_HALO    0                        // 18x18 pixels x 128B fp16 = 41472
#define OFF_BIAS    59136                    // after epilogue alias region [0,59136)
#define SMEM_TOTAL  59392

__device__ unsigned char g_active[4 * NB * NB];
// W in mma-fragment order: [tap][nt][ks][lane] -> uint2 {b0, b1}
__device__ __align__(16) uint2 g_wfrag[9 * 8 * 4 * 32];
// NHWC fp16 image of x (active windows only are valid)
__device__ __align__(16) __half g_x16[4 * H * H * CIN];

// tile-assignment tables (packed nibbles, index by wid)
#define STARTS_A 0xCBA86420u
#define COUNTS_A 0x21122222u
#define STARTS_B 0xCA876420u
#define COUNTS_B 0x22211222u

// ---------------- helpers ----------------
__device__ __forceinline__ uint32_t smem_u32(const void* p) {
    uint32_t a;
    asm("{ .reg .u64 t; cvta.to.shared.u64 t, %1; cvt.u32.u64 %0, t; }" : "=r"(a) : "l"(p));
    return a;
}
__device__ __forceinline__ void ldsm_x4(uint32_t* r, uint32_t addr) {
    asm volatile("ldmatrix.sync.aligned.m8n8.x4.shared.b16 {%0,%1,%2,%3}, [%4];"
        : "=r"(r[0]), "=r"(r[1]), "=r"(r[2]), "=r"(r[3]) : "r"(addr));
}
__device__ __forceinline__ void mma16816(float* d, const uint32_t* a, uint32_t b0, uint32_t b1) {
    asm volatile("mma.sync.aligned.m16n8k16.row.col.f32.f16.f16.f32 "
        "{%0,%1,%2,%3}, {%4,%5,%6,%7}, {%8,%9}, {%0,%1,%2,%3};"
        : "+f"(d[0]), "+f"(d[1]), "+f"(d[2]), "+f"(d[3])
        : "r"(a[0]), "r"(a[1]), "r"(a[2]), "r"(a[3]), "r"(b0), "r"(b1));
}
__device__ __forceinline__ uint32_t pack2(__half a, __half b) {
    return ((uint32_t)__half_as_ushort(b) << 16) | __half_as_ushort(a);
}
__device__ __forceinline__ void cp_async16(uint32_t dst, const void* src, bool pred) {
    asm volatile("cp.async.cg.shared.global [%0], [%1], 16, %2;"
        :: "r"(dst), "l"(src), "r"(pred ? 16u : 0u) : "memory");
}

// ---------------- Kernel 0: W fragment prep ----------------
__global__ void sbnet_wprep_kernel(const float* __restrict__ w) {
    int i = blockIdx.x * 256 + threadIdx.x;
    if (i >= 9 * 8 * 4 * 32) return;
    int tap  = i >> 10;
    int rem  = i & 1023;
    int nt   = rem >> 7;
    int ks   = (rem >> 5) & 3;
    int lane = rem & 31;
    int co = nt * 8 + (lane >> 2);
    int k0 = ks * 16 + (lane & 3) * 2;
    const float* wc = w + (size_t)co * CIN * 9 + tap;
    uint32_t b0 = pack2(__float2half(wc[(size_t)k0 * 9]),
                        __float2half(wc[(size_t)(k0 + 1) * 9]));
    uint32_t b1 = pack2(__float2half(wc[(size_t)(k0 + 8) * 9]),
                        __float2half(wc[(size_t)(k0 + 9) * 9]));
    g_wfrag[i] = make_uint2(b0, b1);
}

// ---------------- Kernel 1: block activity ----------------
__global__ void sbnet_mask_kernel(const float* __restrict__ mask, int n_total) {
    int idx = blockIdx.x * blockDim.x + threadIdx.x;
    if (idx >= n_total) return;
    int bx = idx % NB;
    int by = (idx / NB) % NB;
    int n  = idx / (NB * NB);
    int r0 = by * BS - 1, c0 = bx * BS - 1;
    float m = -1e30f;
    for (int r = 0; r < 16; ++r) {
        int rr = r0 + r;
        if (rr < 0 || rr >= H) continue;
        const float* mrow = mask + ((long)n * H + rr) * H;
        int clo = (c0 < 0) ? 1 : 0;
        int chi = (c0 + 16 > H) ? 15 : 16;
        for (int c = clo; c < chi; ++c) m = fmaxf(m, mrow[c0 + c]);
    }
    g_active[idx] = (m > 0.5f) ? 1 : 0;
}

// ---------------- Kernel 2: convert active windows to NHWC fp16 ----------------
__global__ void __launch_bounds__(256)
sbnet_cvt_kernel(const float* __restrict__ x) {
    __shared__ float s[16][256];
    const int blk = blockIdx.x;
    if (!g_active[blk]) return;
    const int tid = threadIdx.x;
    const int bxy = blk & (NB * NB - 1);
    const int n   = blk >> 10;
    const int bx = bxy % NB, by = bxy / NB;
    const int r0 = by * BS - 1, c0 = bx * BS - 1;

    const int r = tid >> 4, c = tid & 15;       // this thread's write pixel
    const int rr = r0 + r, cc = c0 + c;
    const bool wok = (rr >= 0 && rr < H && cc >= 0 && cc < H);
    __half* dst = g_x16 + (((size_t)n * H + (wok ? rr : 0)) * H + (wok ? cc : 0)) * CIN;

    for (int chunk = 0; chunk < 4; ++chunk) {
        __syncthreads();
        // stage 16 cin x 256 px (read-coalesced)
        #pragma unroll
        for (int it = 0; it < 16; ++it) {
            int i  = it * 256 + tid;
            int ci = i >> 8, px = i & 255;
            int pr = r0 + (px >> 4), pc = c0 + (px & 15);
            float v = 0.0f;
            if (pr >= 0 && pr < H && pc >= 0 && pc < H)
                v = x[((size_t)(n * CIN + chunk * 16 + ci)) * HH + (size_t)pr * H + pc];
            s[ci][px] = v;
        }
        __syncthreads();
        if (wok) {
            uint32_t u[8];
            #pragma unroll
            for (int k = 0; k < 8; ++k)
                u[k] = pack2(__float2half(s[2 * k][tid]), __float2half(s[2 * k + 1][tid]));
            *(uint4*)(dst + chunk * 16)     = make_uint4(u[0], u[1], u[2], u[3]);
            *(uint4*)(dst + chunk * 16 + 8) = make_uint4(u[4], u[5], u[6], u[7]);
        }
    }
}

// ---------------- Kernel 3: HMMA block conv ----------------
__global__ void __launch_bounds__(NTHR, 2)
sbnet_mma_kernel(const float* __restrict__ bias, float* __restrict__ out) {
    extern __shared__ char smem[];
    const int tid  = threadIdx.x;
    const int wid  = tid >> 5;
    const int lane = tid & 31;
    const int bx = blockIdx.x % NB;
    const int by = blockIdx.x / NB;
    const int n  = blockIdx.y;

    if (!g_active[n * NB * NB + blockIdx.x]) {
        for (int i = tid; i < COUT * BS * BS; i += NTHR) {
            int co = i / (BS * BS);
            int rem = i % (BS * BS);
            int y = rem / BS, xx = rem % BS;
            out[((size_t)(n * COUT + co)) * HH + (size_t)(by * BS + y) * H + bx * BS + xx] = 0.0f;
        }
        return;
    }

    const uint32_t smem_base = smem_u32(smem);
    float* s_bias = (float*)(smem + OFF_BIAS);
    if (tid < COUT) s_bias[tid] = bias[tid];

    // ---- halo load: 18x18 pixels x 128B fp16, cp.async with zfill ----
    const int r0 = by * BS - 1, c0 = bx * BS - 1;
    const uint32_t halo = smem_base + OFF_HALO;
    for (int i = tid; i < HAL * HAL * 8; i += NTHR) {
        int j   = i & 7;
        int pos = i >> 3;
        int y = pos / HAL, xx = pos % HAL;
        int rr = r0 + y, cc = c0 + xx;
        bool inb = (rr >= 0 && rr < H && cc >= 0 && cc < H);
        const __half* src = g_x16 + (((size_t)n * H + (inb ? rr : 0)) * H + (inb ? cc : 0)) * CIN + j * 8;
        uint32_t dst = halo + (uint32_t)pos * 128 + (((uint32_t)j ^ (pos & 7)) << 4);
        cp_async16(dst, src, inb);
    }
    asm volatile("cp.async.commit_group;" ::: "memory");
    asm volatile("cp.async.wait_group 0;" ::: "memory");
    __syncthreads();

    // ---- tile assignment (parity-balanced across SMSPs) ----
    const int parity = (blockIdx.x + blockIdx.y) & 1;
    const uint32_t starts = parity ? STARTS_B : STARTS_A;
    const uint32_t counts = parity ? COUNTS_B : COUNTS_A;
    const int t0  = (starts >> (4 * wid)) & 15;
    const bool two = (((counts >> (4 * wid)) & 15) == 2);

    const int cA = lane & 15;
    const int ksubA = lane >> 4;

    float acc[2][8][4];
    #pragma unroll
    for (int mt = 0; mt < 2; ++mt)
        #pragma unroll
        for (int nt = 0; nt < 8; ++nt)
            #pragma unroll
            for (int q = 0; q < 4; ++q) acc[mt][nt][q] = 0.0f;

    const uint2* wf = g_wfrag + lane;        // + tap*1024 + nt*128 + ks*32

    #pragma unroll 1
    for (int tap = 0; tap < 9; ++tap) {
        const int dy = tap / 3, dx = tap - dy * 3;
        const uint32_t pm0 = (t0 + dy) * HAL + cA + dx;
        const uint32_t pm1 = pm0 + HAL;
        const uint2* wt = wf + tap * 1024;

        #pragma unroll
        for (int ks = 0; ks < 4; ++ks) {
            uint32_t ah[2][4];
            uint2 b[8];
            {
                uint32_t koff = (uint32_t)(ks * 2 + ksubA);
                ldsm_x4(ah[0], halo + pm0 * 128 + ((koff ^ (pm0 & 7)) << 4));
                if (two)
                    ldsm_x4(ah[1], halo + pm1 * 128 + ((koff ^ (pm1 & 7)) << 4));
            }
            #pragma unroll
            for (int nt = 0; nt < 8; ++nt)
                b[nt] = __ldg(wt + nt * 128 + ks * 32);
            #pragma unroll
            for (int nt = 0; nt < 8; ++nt)
                mma16816(acc[0][nt], ah[0], b[nt].x, b[nt].y);
            if (two) {
                #pragma unroll
                for (int nt = 0; nt < 8; ++nt)
                    mma16816(acc[1][nt], ah[1], b[nt].x, b[nt].y);
            }
        }
    }

    // ---- epilogue: accums -> smem transpose -> coalesced gmem ----
    __syncthreads();               // halo dead -> epi aliasing safe
    float* epi = (float*)smem;     // [224][66]
    const int g  = lane >> 2;
    const int tg = lane & 3;
    #pragma unroll
    for (int mt = 0; mt < 2; ++mt) {
        if (mt == 0 || two) {
            int tile = t0 + mt;
            #pragma unroll
            for (int nt = 0; nt < 8; ++nt) {
                int p  = tile * 16 + g;
                int co = nt * 8 + 2 * tg;
                *(float2*)&epi[p * 66 + co]       = make_float2(acc[mt][nt][0], acc[mt][nt][1]);
                *(float2*)&epi[(p + 8) * 66 + co] = make_float2(acc[mt][nt][2], acc[mt][nt][3]);
            }
        }
    }
    __syncthreads();

    for (int i = tid; i < COUT * BS * BS; i += NTHR) {
        int co = i / (BS * BS);
        int rem = i % (BS * BS);
        int y = rem / BS, xx = rem % BS;
        float val = epi[(y * 16 + xx) * 66 + co] + s_bias[co];
        out[((size_t)(n * COUT + co)) * HH + (size_t)(by * BS + y) * H + bx * BS + xx] = val;
    }
}

extern "C" void kernel_launch(void* const* d_in, const int* in_sizes, int n_in,
                              void* d_out, int out_size) {
    const float* x    = (const float*)d_in[0];
    const float* mask = (const float*)d_in[1];
    const float* w    = (const float*)d_in[2];
    const float* bias = (const float*)d_in[3];
    float* out = (float*)d_out;

    int N = in_sizes[0] / (CIN * H * H);   // 4
    int nblk = N * NB * NB;

    cudaFuncSetAttribute(sbnet_mma_kernel,
                         cudaFuncAttributeMaxDynamicSharedMemorySize, SMEM_TOTAL);

    sbnet_wprep_kernel<<<(9 * 8 * 4 * 32 + 255) / 256, 256>>>(w);
    sbnet_mask_kernel<<<(nblk + 255) / 256, 256>>>(mask, nblk);
    sbnet_cvt_kernel<<<nblk, 256>>>(x);
    sbnet_mma_kernel<<<dim3(NB * NB, (unsigned)N), NTHR, SMEM_TOTAL>>>(bias, out);
}

// round 11
// speedup vs baseline: 1.3196x; 1.3196x over previous
#include <cuda_runtime.h>
#include <cuda_fp16.h>
#include <cstdint>

#define H    448
#define HH   (448*448)
#define CIN  64
#define COUT 64
#define NB   32
#define BS   14
#define HALW 18                      // halo width (pixels)
#define HALR 16                      // halo rows (gather window height)
#define NPOS (HALR*HALW)             // 288 pixels
#define NTHR 256

// ---- dynamic smem layout (bytes) ----
#define OFF_HALO  0                  // 288 pos x 144B (128B data + 16B pad)
#define OFF_RAWA  41472              // 16 cin x 16 rows x 24 f32 = 24576
#define OFF_RAWB  66048
#define OFF_BIAS  90624              // 64 f32
#define SMEM_TOTAL 90880
// epilogue aliases [0, 59136) = 224 x 66 f32 (halo/raw dead by then)

#define RAWP  384                    // floats per cin plane (16*24)

__device__ unsigned char g_active[4 * NB * NB];
// W in mma-fragment order: [tap][nt][ks][lane] -> uint2 {b0, b1}
__device__ __align__(16) uint2 g_wfrag[9 * 8 * 4 * 32];

// balanced tile tables (nibble per wid)
#define STARTS_A 0xCBA86420u
#define COUNTS_A 0x21122222u
#define STARTS_B 0xCA876420u
#define COUNTS_B 0x22211222u

// ---------------- helpers ----------------
__device__ __forceinline__ uint32_t smem_u32(const void* p) {
    uint32_t a;
    asm("{ .reg .u64 t; cvta.to.shared.u64 t, %1; cvt.u32.u64 %0, t; }" : "=r"(a) : "l"(p));
    return a;
}
__device__ __forceinline__ void ldsm_x4(uint32_t* r, uint32_t addr) {
    asm volatile("ldmatrix.sync.aligned.m8n8.x4.shared.b16 {%0,%1,%2,%3}, [%4];"
        : "=r"(r[0]), "=r"(r[1]), "=r"(r[2]), "=r"(r[3]) : "r"(addr));
}
__device__ __forceinline__ void mma16816(float* d, const uint32_t* a, uint32_t b0, uint32_t b1) {
    asm volatile("mma.sync.aligned.m16n8k16.row.col.f32.f16.f16.f32 "
        "{%0,%1,%2,%3}, {%4,%5,%6,%7}, {%8,%9}, {%0,%1,%2,%3};"
        : "+f"(d[0]), "+f"(d[1]), "+f"(d[2]), "+f"(d[3])
        : "r"(a[0]), "r"(a[1]), "r"(a[2]), "r"(a[3]), "r"(b0), "r"(b1));
}
__device__ __forceinline__ uint32_t pack2(__half a, __half b) {
    return ((uint32_t)__half_as_ushort(b) << 16) | __half_as_ushort(a);
}
__device__ __forceinline__ void cp_async16(uint32_t dst, const void* src, bool pred) {
    asm volatile("cp.async.cg.shared.global [%0], [%1], 16, %2;"
        :: "r"(dst), "l"(src), "r"(pred ? 16u : 0u) : "memory");
}

// ---------------- Kernel 0: W fragment prep ----------------
__global__ void sbnet_wprep_kernel(const float* __restrict__ w) {
    int i = blockIdx.x * 256 + threadIdx.x;
    if (i >= 9 * 8 * 4 * 32) return;
    int tap  = i >> 10;
    int rem  = i & 1023;
    int nt   = rem >> 7;
    int ks   = (rem >> 5) & 3;
    int lane = rem & 31;
    int co = nt * 8 + (lane >> 2);
    int k0 = ks * 16 + (lane & 3) * 2;
    const float* wc = w + (size_t)co * CIN * 9 + tap;
    uint32_t b0 = pack2(__float2half(wc[(size_t)k0 * 9]),
                        __float2half(wc[(size_t)(k0 + 1) * 9]));
    uint32_t b1 = pack2(__float2half(wc[(size_t)(k0 + 8) * 9]),
                        __float2half(wc[(size_t)(k0 + 9) * 9]));
    g_wfrag[i] = make_uint2(b0, b1);
}

// ---------------- Kernel 1: block activity ----------------
__global__ void sbnet_mask_kernel(const float* __restrict__ mask, int n_total) {
    int idx = blockIdx.x * blockDim.x + threadIdx.x;
    if (idx >= n_total) return;
    int bx = idx % NB;
    int by = (idx / NB) % NB;
    int n  = idx / (NB * NB);
    int r0 = by * BS - 1, c0 = bx * BS - 1;
    float m = -1e30f;
    for (int r = 0; r < 16; ++r) {
        int rr = r0 + r;
        if (rr < 0 || rr >= H) continue;
        const float* mrow = mask + ((long)n * H + rr) * H;
        int clo = (c0 < 0) ? 1 : 0;
        int chi = (c0 + 16 > H) ? 15 : 16;
        for (int c = clo; c < chi; ++c) m = fmaxf(m, mrow[c0 + c]);
    }
    g_active[idx] = (m > 0.5f) ? 1 : 0;
}

// ---------------- Kernel 2: fused HMMA block conv ----------------
__global__ void __launch_bounds__(NTHR, 2)
sbnet_mma_kernel(const float* __restrict__ x, const float* __restrict__ bias,
                 float* __restrict__ out) {
    extern __shared__ char smem[];
    const int tid  = threadIdx.x;
    const int wid  = tid >> 5;
    const int lane = tid & 31;
    const int bx = blockIdx.x % NB;
    const int by = blockIdx.x / NB;
    const int n  = blockIdx.y;

    // per-lane pixel start for epilogue sweeps (p = lane, then +32 per round)
    const int ly0 = lane / BS;
    const int lx0 = lane - ly0 * BS;

    if (!g_active[n * NB * NB + blockIdx.x]) {
        // inactive: zero 64 x 14 x 14 block with incremental addressing
        #pragma unroll 1
        for (int cog = 0; cog < 8; ++cog) {
            int co = wid + cog * 8;
            float* op = out + ((size_t)(n * COUT + co)) * HH + (size_t)(by * BS) * H + bx * BS;
            int yy = ly0, xq = lx0;
            #pragma unroll
            for (int rnd = 0; rnd < 7; ++rnd) {
                if (rnd * 32 + lane < BS * BS)
                    op[(size_t)yy * H + xq] = 0.0f;
                yy += 2; xq += 4;
                if (xq >= BS) { xq -= BS; ++yy; }
            }
        }
        return;
    }

    const uint32_t smem_base = smem_u32(smem);
    float* s_bias = (float*)(smem + OFF_BIAS);
    if (tid < COUT) s_bias[tid] = bias[tid];

    const int r0 = by * BS - 1, c0 = bx * BS - 1;
    const int cb0 = (c0 < 0) ? 0 : (c0 & ~3);
    const int coff = c0 - cb0;                  // raw col idx = coff + xx
    const uint32_t halo = smem_base + OFF_HALO;

    // issue chunk's 16-cin raw tile (16 rows x 24 aligned cols) into buffer
    auto issue_load = [&](int chunk, uint32_t rb) {
        const float* xb = x + ((size_t)(n * CIN + chunk * 16)) * HH;
        #pragma unroll
        for (int it = 0; it < 6; ++it) {
            int i = it * 256 + tid;             // 0..1535
            int j = i % 6;
            int rest = i / 6;
            int y  = rest & 15;
            int ci = rest >> 4;
            int rr = r0 + y;
            int s  = cb0 + j * 4;
            bool inb = (rr >= 0 && rr < H && s < H);
            const float* src = xb + (size_t)ci * HH + (inb ? (size_t)rr * H + s : 0);
            cp_async16(rb + (uint32_t)(ci * RAWP + y * 24 + j * 4) * 4, src, inb);
        }
        asm volatile("cp.async.commit_group;" ::: "memory");
    };

    // convert one chunk from raw buffer into halo columns [chunk*32, chunk*32+32)
    auto convert = [&](int chunk, const float* raw) {
        #pragma unroll 1
        for (int pos = tid; pos < NPOS; pos += NTHR) {
            int y  = pos / HALW;
            int xx = pos - y * HALW;
            int cc = c0 + xx;
            bool ok = (cc >= 0 && cc < H);
            int idx = ok ? (y * 24 + coff + xx) : 0;
            uint32_t hu[8];
            #pragma unroll
            for (int k = 0; k < 8; ++k) {
                float v0 = raw[(2 * k) * RAWP + idx];
                float v1 = raw[(2 * k + 1) * RAWP + idx];
                if (!ok) { v0 = 0.0f; v1 = 0.0f; }
                hu[k] = pack2(__float2half(v0), __float2half(v1));
            }
            char* dst = smem + OFF_HALO + pos * 144 + chunk * 32;
            *(uint4*)dst        = make_uint4(hu[0], hu[1], hu[2], hu[3]);
            *(uint4*)(dst + 16) = make_uint4(hu[4], hu[5], hu[6], hu[7]);
        }
    };

    const float* rawA = (const float*)(smem + OFF_RAWA);
    const float* rawB = (const float*)(smem + OFF_RAWB);
    const uint32_t rbA = smem_base + OFF_RAWA;
    const uint32_t rbB = smem_base + OFF_RAWB;

    // double-buffered prologue: loads overlap converts
    issue_load(0, rbA);
    issue_load(1, rbB);
    asm volatile("cp.async.wait_group 1;" ::: "memory");
    __syncthreads();
    convert(0, rawA);
    __syncthreads();
    issue_load(2, rbA);
    asm volatile("cp.async.wait_group 1;" ::: "memory");
    __syncthreads();
    convert(1, rawB);
    __syncthreads();
    issue_load(3, rbB);
    asm volatile("cp.async.wait_group 1;" ::: "memory");
    __syncthreads();
    convert(2, rawA);
    asm volatile("cp.async.wait_group 0;" ::: "memory");
    __syncthreads();
    convert(3, rawB);
    __syncthreads();

    // ---- balanced tile assignment ----
    const int parity = (blockIdx.x + blockIdx.y) & 1;
    const uint32_t starts = parity ? STARTS_B : STARTS_A;
    const uint32_t counts = parity ? COUNTS_B : COUNTS_A;
    const int t0  = (starts >> (4 * wid)) & 15;
    const bool two = (((counts >> (4 * wid)) & 15) == 2);

    const int cA = lane & 15;
    const uint32_t kbase = (uint32_t)(lane >> 4) * 16;   // ksubA*16

    float acc[2][8][4];
    #pragma unroll
    for (int mt = 0; mt < 2; ++mt)
        #pragma unroll
        for (int nt = 0; nt < 8; ++nt)
            #pragma unroll
            for (int q = 0; q < 4; ++q) acc[mt][nt][q] = 0.0f;

    const uint2* wf = g_wfrag + lane;        // + tap*1024 + nt*128 + ks*32

    #pragma unroll 1
    for (int tap = 0; tap < 9; ++tap) {
        const int dy = tap / 3, dx = tap - dy * 3;
        // ldsm base addresses (144B pixel stride, no swizzle)
        const uint32_t a0 = halo + (uint32_t)((t0 + dy) * HALW + cA + dx) * 144 + kbase;
        const uint32_t a1 = a0 + HALW * 144;
        const uint2* wt = wf + tap * 1024;

        #pragma unroll
        for (int ks = 0; ks < 4; ++ks) {
            uint32_t ah[2][4];
            uint2 b[8];
            ldsm_x4(ah[0], a0 + ks * 32);
            if (two) ldsm_x4(ah[1], a1 + ks * 32);
            #pragma unroll
            for (int nt = 0; nt < 8; ++nt)
                b[nt] = __ldg(wt + nt * 128 + ks * 32);
            #pragma unroll
            for (int nt = 0; nt < 8; ++nt)
                mma16816(acc[0][nt], ah[0], b[nt].x, b[nt].y);
            if (two) {
                #pragma unroll
                for (int nt = 0; nt < 8; ++nt)
                    mma16816(acc[1][nt], ah[1], b[nt].x, b[nt].y);
            }
        }
    }

    // ---- epilogue: accums -> smem transpose -> coalesced gmem ----
    __syncthreads();               // halo/raw dead -> epi aliasing safe
    float* epi = (float*)smem;     // [224][66]
    {
        const int g  = lane >> 2;
        const int tg = lane & 3;
        #pragma unroll
        for (int mt = 0; mt < 2; ++mt) {
            if (mt == 0 || two) {
                int tile = t0 + mt;
                #pragma unroll
                for (int nt = 0; nt < 8; ++nt) {
                    int p  = tile * 16 + g;
                    int co = nt * 8 + 2 * tg;
                    *(float2*)&epi[p * 66 + co]       = make_float2(acc[mt][nt][0], acc[mt][nt][1]);
                    *(float2*)&epi[(p + 8) * 66 + co] = make_float2(acc[mt][nt][2], acc[mt][nt][3]);
                }
            }
        }
    }
    __syncthreads();

    // warp sweeps: co = wid + 8*cog, lanes cover 196 pixels incrementally
    #pragma unroll 1
    for (int cog = 0; cog < 8; ++cog) {
        int co = wid + cog * 8;
        float bv = s_bias[co];
        float* op = out + ((size_t)(n * COUT + co)) * HH + (size_t)(by * BS) * H + bx * BS;
        int yy = ly0, xq = lx0;
        #pragma unroll
        for (int rnd = 0; rnd < 7; ++rnd) {
            if (rnd * 32 + lane < BS * BS)
                op[(size_t)yy * H + xq] = epi[(yy * 16 + xq) * 66 + co] + bv;
            yy += 2; xq += 4;
            if (xq >= BS) { xq -= BS; ++yy; }
        }
    }
}

extern "C" void kernel_launch(void* const* d_in, const int* in_sizes, int n_in,
                              void* d_out, int out_size) {
    const float* x    = (const float*)d_in[0];
    const float* mask = (const float*)d_in[1];
    const float* w    = (const float*)d_in[2];
    const float* bias = (const float*)d_in[3];
    float* out = (float*)d_out;

    int N = in_sizes[0] / (CIN * H * H);   // 4
    int nblk = N * NB * NB;

    cudaFuncSetAttribute(sbnet_mma_kernel,
                         cudaFuncAttributeMaxDynamicSharedMemorySize, SMEM_TOTAL);

    sbnet_wprep_kernel<<<(9 * 8 * 4 * 32 + 255) / 256, 256>>>(w);
    sbnet_mask_kernel<<<(nblk + 255) / 256, 256>>>(mask, nblk);
    sbnet_mma_kernel<<<dim3(NB * NB, (unsigned)N), NTHR, SMEM_TOTAL>>>(x, bias, out);
}

// round 12
// speedup vs baseline: 1.4104x; 1.0688x over previous
#include <cuda_runtime.h>
#include <cuda_fp16.h>
#include <cstdint>

#define H    448
#define HH   (448*448)
#define CIN  64
#define COUT 64
#define NB   32
#define BS   14
#define HALW 18                      // halo width (pixels)
#define HALR 16                      // halo rows
#define NPOS (HALR*HALW)             // 288
#define NTHR 256

// ---- dynamic smem layout (bytes) ----
#define OFF_HALO  0                  // 288 pos x 144B
#define OFF_WTAB  41472              // 73728B W table (ldsm layout)
#define OFF_RAWA  41472              // aliases WTAB during halo build
#define OFF_RAWB  66048
#define OFF_BIAS  115200             // 64 f32
#define SMEM_TOTAL 115456
// epilogue aliases [0, 59136) = 224 x 66 f32

#define RAWP  384                    // floats per cin plane (16*24)

__device__ unsigned char g_active[4 * NB * NB];
// W table, ldmatrix-native: offset(tap,nt,ks,half,row)= (((tap*8+nt)*4+ks)*2+half)*128 + row*16
__device__ __align__(16) unsigned char g_wtab[9 * 8 * 4 * 2 * 128];

// balanced tile tables (nibble per wid)
#define STARTS_A 0xCBA86420u
#define COUNTS_A 0x21122222u
#define STARTS_B 0xCA876420u
#define COUNTS_B 0x22211222u

// ---------------- helpers ----------------
__device__ __forceinline__ uint32_t smem_u32(const void* p) {
    uint32_t a;
    asm("{ .reg .u64 t; cvta.to.shared.u64 t, %1; cvt.u32.u64 %0, t; }" : "=r"(a) : "l"(p));
    return a;
}
__device__ __forceinline__ void ldsm_x4(uint32_t* r, uint32_t addr) {
    asm volatile("ldmatrix.sync.aligned.m8n8.x4.shared.b16 {%0,%1,%2,%3}, [%4];"
        : "=r"(r[0]), "=r"(r[1]), "=r"(r[2]), "=r"(r[3]) : "r"(addr));
}
__device__ __forceinline__ void mma16816(float* d, const uint32_t* a, uint32_t b0, uint32_t b1) {
    asm volatile("mma.sync.aligned.m16n8k16.row.col.f32.f16.f16.f32 "
        "{%0,%1,%2,%3}, {%4,%5,%6,%7}, {%8,%9}, {%0,%1,%2,%3};"
        : "+f"(d[0]), "+f"(d[1]), "+f"(d[2]), "+f"(d[3])
        : "r"(a[0]), "r"(a[1]), "r"(a[2]), "r"(a[3]), "r"(b0), "r"(b1));
}
__device__ __forceinline__ uint32_t pack2(__half a, __half b) {
    return ((uint32_t)__half_as_ushort(b) << 16) | __half_as_ushort(a);
}
__device__ __forceinline__ void cp_async16(uint32_t dst, const void* src, bool pred) {
    asm volatile("cp.async.cg.shared.global [%0], [%1], 16, %2;"
        :: "r"(dst), "l"(src), "r"(pred ? 16u : 0u) : "memory");
}

// ---------------- Kernel 0: combined prep (W table + block activity) ----------------
__global__ void sbnet_prep_kernel(const float* __restrict__ w,
                                  const float* __restrict__ mask, int n_total) {
    if (blockIdx.x < 18) {
        int i = blockIdx.x * 256 + threadIdx.x;      // 0..4607 16B rows
        int tap = i / 512;
        int r   = i & 511;
        int nt = r >> 6, ks = (r >> 4) & 3, half = (r >> 3) & 1, row = r & 7;
        int co = nt * 8 + row;
        int k0 = ks * 16 + half * 8;
        const float* wc = w + ((size_t)co * CIN + k0) * 9 + tap;
        uint32_t u[4];
        #pragma unroll
        for (int c = 0; c < 4; ++c)
            u[c] = pack2(__float2half(wc[(size_t)(2 * c) * 9]),
                         __float2half(wc[(size_t)(2 * c + 1) * 9]));
        *(uint4*)(g_wtab + (size_t)i * 16) = make_uint4(u[0], u[1], u[2], u[3]);
        return;
    }
    int idx = (blockIdx.x - 18) * 256 + threadIdx.x;
    if (idx >= n_total) return;
    int bx = idx % NB;
    int by = (idx / NB) % NB;
    int n  = idx / (NB * NB);
    int r0 = by * BS - 1, c0 = bx * BS - 1;
    float m = -1e30f;
    for (int r = 0; r < 16; ++r) {
        int rr = r0 + r;
        if (rr < 0 || rr >= H) continue;
        const float* mrow = mask + ((long)n * H + rr) * H;
        int clo = (c0 < 0) ? 1 : 0;
        int chi = (c0 + 16 > H) ? 15 : 16;
        for (int c = clo; c < chi; ++c) m = fmaxf(m, mrow[c0 + c]);
    }
    g_active[idx] = (m > 0.5f) ? 1 : 0;
}

// ---------------- Kernel 1: fused HMMA block conv ----------------
__global__ void __launch_bounds__(NTHR, 2)
sbnet_mma_kernel(const float* __restrict__ x, const float* __restrict__ bias,
                 float* __restrict__ out) {
    extern __shared__ char smem[];
    const int tid  = threadIdx.x;
    const int wid  = tid >> 5;
    const int lane = tid & 31;
    const int bx = blockIdx.x % NB;
    const int by = blockIdx.x / NB;
    const int n  = blockIdx.y;

    const int ly0 = lane / BS;
    const int lx0 = lane - ly0 * BS;

    if (!g_active[n * NB * NB + blockIdx.x]) {
        #pragma unroll 1
        for (int cog = 0; cog < 8; ++cog) {
            int co = wid + cog * 8;
            float* op = out + ((size_t)(n * COUT + co)) * HH + (size_t)(by * BS) * H + bx * BS;
            int yy = ly0, xq = lx0;
            #pragma unroll
            for (int rnd = 0; rnd < 7; ++rnd) {
                if (rnd * 32 + lane < BS * BS)
                    op[(size_t)yy * H + xq] = 0.0f;
                yy += 2; xq += 4;
                if (xq >= BS) { xq -= BS; ++yy; }
            }
        }
        return;
    }

    const uint32_t smem_base = smem_u32(smem);
    float* s_bias = (float*)(smem + OFF_BIAS);
    if (tid < COUT) s_bias[tid] = bias[tid];

    const int r0 = by * BS - 1, c0 = bx * BS - 1;
    const int cb0 = (c0 < 0) ? 0 : (c0 & ~3);
    const int coff = c0 - cb0;
    const uint32_t halo = smem_base + OFF_HALO;

    auto issue_load = [&](int chunk, uint32_t rb) {
        const float* xb = x + ((size_t)(n * CIN + chunk * 16)) * HH;
        #pragma unroll
        for (int it = 0; it < 6; ++it) {
            int i = it * 256 + tid;
            int j = i % 6;
            int rest = i / 6;
            int y  = rest & 15;
            int ci = rest >> 4;
            int rr = r0 + y;
            int s  = cb0 + j * 4;
            bool inb = (rr >= 0 && rr < H && s < H);
            const float* src = xb + (size_t)ci * HH + (inb ? (size_t)rr * H + s : 0);
            cp_async16(rb + (uint32_t)(ci * RAWP + y * 24 + j * 4) * 4, src, inb);
        }
        asm volatile("cp.async.commit_group;" ::: "memory");
    };

    auto convert = [&](int chunk, const float* raw) {
        #pragma unroll 1
        for (int pos = tid; pos < NPOS; pos += NTHR) {
            int y  = pos / HALW;
            int xx = pos - y * HALW;
            int cc = c0 + xx;
            bool ok = (cc >= 0 && cc < H);
            int idx = ok ? (y * 24 + coff + xx) : 0;
            uint32_t hu[8];
            #pragma unroll
            for (int k = 0; k < 8; ++k) {
                float v0 = raw[(2 * k) * RAWP + idx];
                float v1 = raw[(2 * k + 1) * RAWP + idx];
                if (!ok) { v0 = 0.0f; v1 = 0.0f; }
                hu[k] = pack2(__float2half(v0), __float2half(v1));
            }
            char* dst = smem + OFF_HALO + pos * 144 + chunk * 32;
            *(uint4*)dst        = make_uint4(hu[0], hu[1], hu[2], hu[3]);
            *(uint4*)(dst + 16) = make_uint4(hu[4], hu[5], hu[6], hu[7]);
        }
    };

    const float* rawA = (const float*)(smem + OFF_RAWA);
    const float* rawB = (const float*)(smem + OFF_RAWB);
    const uint32_t rbA = smem_base + OFF_RAWA;
    const uint32_t rbB = smem_base + OFF_RAWB;

    issue_load(0, rbA);
    issue_load(1, rbB);
    asm volatile("cp.async.wait_group 1;" ::: "memory");
    __syncthreads();
    convert(0, rawA);
    __syncthreads();
    issue_load(2, rbA);
    asm volatile("cp.async.wait_group 1;" ::: "memory");
    __syncthreads();
    convert(1, rawB);
    __syncthreads();
    issue_load(3, rbB);
    asm volatile("cp.async.wait_group 1;" ::: "memory");
    __syncthreads();
    convert(2, rawA);
    asm volatile("cp.async.wait_group 0;" ::: "memory");
    __syncthreads();
    convert(3, rawB);
    __syncthreads();               // raw buffers dead -> stage W into their region

    // ---- stage W table (73728B, 4608 x 16B) ----
    {
        const uint4* wsrc = (const uint4*)g_wtab;
        uint32_t wdst = smem_base + OFF_WTAB;
        #pragma unroll
        for (int it = 0; it < 18; ++it) {
            int i = it * 256 + tid;
            cp_async16(wdst + (uint32_t)i * 16, wsrc + i, true);
        }
        asm volatile("cp.async.commit_group;" ::: "memory");
        asm volatile("cp.async.wait_group 0;" ::: "memory");
        __syncthreads();
    }

    // ---- balanced tile assignment ----
    const int parity = (blockIdx.x + blockIdx.y) & 1;
    const uint32_t starts = parity ? STARTS_B : STARTS_A;
    const uint32_t counts = parity ? COUNTS_B : COUNTS_A;
    const int t0  = (starts >> (4 * wid)) & 15;
    const bool two = (((counts >> (4 * wid)) & 15) == 2);

    const int cA = lane & 15;
    const uint32_t kbase = (uint32_t)(lane >> 4) * 16;

    // per-lane B base: nt_l*1024 + half_l*128 + row*16
    const uint32_t wlane = smem_base + OFF_WTAB +
        (uint32_t)(lane >> 4) * 1024 + (uint32_t)((lane >> 3) & 1) * 128 +
        (uint32_t)(lane & 7) * 16;

    float acc[2][8][4];
    #pragma unroll
    for (int mt = 0; mt < 2; ++mt)
        #pragma unroll
        for (int nt = 0; nt < 8; ++nt)
            #pragma unroll
            for (int q = 0; q < 4; ++q) acc[mt][nt][q] = 0.0f;

    #pragma unroll 1
    for (int tap = 0; tap < 9; ++tap) {
        const int dy = tap / 3, dx = tap - dy * 3;
        const uint32_t a0 = halo + (uint32_t)((t0 + dy) * HALW + cA + dx) * 144 + kbase;
        const uint32_t a1 = a0 + HALW * 144;
        const uint32_t wt = wlane + (uint32_t)tap * 8192;

        #pragma unroll
        for (int ks = 0; ks < 4; ++ks) {
            uint32_t ah[2][4];
            uint32_t bb[4][4];                   // [ntpair][4 regs = 2 fragments]
            ldsm_x4(ah[0], a0 + ks * 32);
            if (two) ldsm_x4(ah[1], a1 + ks * 32);
            #pragma unroll
            for (int np = 0; np < 4; ++np)
                ldsm_x4(bb[np], wt + (uint32_t)np * 2048 + (uint32_t)ks * 256);
            #pragma unroll
            for (int nt = 0; nt < 8; ++nt)
                mma16816(acc[0][nt], ah[0], bb[nt >> 1][(nt & 1) * 2], bb[nt >> 1][(nt & 1) * 2 + 1]);
            if (two) {
                #pragma unroll
                for (int nt = 0; nt < 8; ++nt)
                    mma16816(acc[1][nt], ah[1], bb[nt >> 1][(nt & 1) * 2], bb[nt >> 1][(nt & 1) * 2 + 1]);
            }
        }
    }

    // ---- epilogue ----
    __syncthreads();
    float* epi = (float*)smem;     // [224][66]
    {
        const int g  = lane >> 2;
        const int tg = lane & 3;
        #pragma unroll
        for (int mt = 0; mt < 2; ++mt) {
            if (mt == 0 || two) {
                int tile = t0 + mt;
                #pragma unroll
                for (int nt = 0; nt < 8; ++nt) {
                    int p  = tile * 16 + g;
                    int co = nt * 8 + 2 * tg;
                    *(float2*)&epi[p * 66 + co]       = make_float2(acc[mt][nt][0], acc[mt][nt][1]);
                    *(float2*)&epi[(p + 8) * 66 + co] = make_float2(acc[mt][nt][2], acc[mt][nt][3]);
                }
            }
        }
    }
    __syncthreads();

    #pragma unroll 1
    for (int cog = 0; cog < 8; ++cog) {
        int co = wid + cog * 8;
        float bv = s_bias[co];
        float* op = out + ((size_t)(n * COUT + co)) * HH + (size_t)(by * BS) * H + bx * BS;
        int yy = ly0, xq = lx0;
        #pragma unroll
        for (int rnd = 0; rnd < 7; ++rnd) {
            if (rnd * 32 + lane < BS * BS)
                op[(size_t)yy * H + xq] = epi[(yy * 16 + xq) * 66 + co] + bv;
            yy += 2; xq += 4;
            if (xq >= BS) { xq -= BS; ++yy; }
        }
    }
}

extern "C" void kernel_launch(void* const* d_in, const int* in_sizes, int n_in,
                              void* d_out, int out_size) {
    const float* x    = (const float*)d_in[0];
    const float* mask = (const float*)d_in[1];
    const float* w    = (const float*)d_in[2];
    const float* bias = (const float*)d_in[3];
    float* out = (float*)d_out;

    int N = in_sizes[0] / (CIN * H * H);   // 4
    int nblk = N * NB * NB;

    cudaFuncSetAttribute(sbnet_mma_kernel,
                         cudaFuncAttributeMaxDynamicSharedMemorySize, SMEM_TOTAL);

    sbnet_prep_kernel<<<18 + (nblk + 255) / 256, 256>>>(w, mask, nblk);
    sbnet_mma_kernel<<<dim3(NB * NB, (unsigned)N), NTHR, SMEM_TOTAL>>>(x, bias, out);
}